// round 6
// baseline (speedup 1.0000x reference)
#include <cuda_runtime.h>
#include <cuda_bf16.h>
#include <cstdint>

// Inputs (metadata order):
//   d_in[0] weight : float32 [N_NODES * 128]
//   d_in[1] cj     : float32 [N_NODES]
//   d_in[2] ci     : float32 [N_NODES]
//   d_in[3] src    : int32   [N_EDGES]
//   d_in[4] dst    : int32   [N_EDGES]
// Output: float32 [N_NODES * 128]
//
// h[d] = ci[d] * sum_{e: dst_e = d} weight[src_e] * cj[src_e]
//
// 4-kernel pipeline:
//   k_pre     : FUSED (a) dst histogram with per-edge rank capture
//                     (b) W' = weight * cj precompute into scratch
//               (disjoint block ranges; atomic-bound hist overlaps the
//               bandwidth-bound precompute inside one launch)
//   k_scan    : exclusive scan of counts -> g_offsets, inclusive -> g_cursor
//               (single launch; cross-block prefix via publish/poll words)
//   k_scatter : pos = offsets[dst] + rank  (NO atomics), write src id
//   k_gather  : one warp per dst node; lane-coalesced edge-id loads + shfl;
//               register accumulation of W'[src]; single 512B store

static constexpr int MAX_NODES  = 100000;
static constexpr int MAX_EDGES  = 1600000;
static constexpr int FEAT4      = 32;           // 128 floats = 32 float4
static constexpr int SCAN_BLOCK = 1024;
static constexpr int MAX_SCAN_BLOCKS = (MAX_NODES + SCAN_BLOCK - 1) / SCAN_BLOCK; // 98

__device__ int    g_counts[MAX_NODES];           // zero-init; re-zeroed by gather
__device__ int    g_offsets[MAX_NODES];          // segment start
__device__ int    g_cursor[MAX_NODES];           // segment end (inclusive prefix)
__device__ unsigned int g_pub[MAX_SCAN_BLOCKS];  // zero-init; re-zeroed by scatter
__device__ int    g_rank[MAX_EDGES];             // per-edge rank within its dst
__device__ int    g_edge_src[MAX_EDGES];         // dst-sorted src ids
__device__ float4 g_ws4[MAX_NODES * FEAT4];      // W' = weight * cj (51.2 MB scratch)

// ---------------- fused histogram + weight pre-scale ----------------

__global__ void __launch_bounds__(256)
k_pre(const float4* __restrict__ weight4,
      const float*  __restrict__ cj,
      const int4*   __restrict__ dst4,
      const int*    __restrict__ dst,
      int n_quads, int n_edges, int n_nodes, int hist_blocks)
{
    if ((int)blockIdx.x < hist_blocks) {
        // ---- histogram of dst, capturing per-edge ranks ----
        int q = blockIdx.x * 256 + threadIdx.x;
        if (q < n_quads) {
            int4 d = __ldg(dst4 + q);
            int4 r;
            r.x = atomicAdd(&g_counts[d.x], 1);
            r.y = atomicAdd(&g_counts[d.y], 1);
            r.z = atomicAdd(&g_counts[d.z], 1);
            r.w = atomicAdd(&g_counts[d.w], 1);
            ((int4*)g_rank)[q] = r;               // coalesced rank store
        }
        int t = n_quads * 4 + q;
        if (q < (n_edges - n_quads * 4))
            g_rank[t] = atomicAdd(&g_counts[dst[t]], 1);
    } else {
        // ---- W' = weight * cj ----
        int i = ((int)blockIdx.x - hist_blocks) * 256 + threadIdx.x;
        int total = n_nodes * FEAT4;
        if (i < total) {
            int row = i >> 5;                     // 32 float4 per row
            float s = __ldg(cj + row);            // warp-uniform broadcast
            float4 v = __ldg(weight4 + i);
            v.x *= s; v.y *= s; v.z *= s; v.w *= s;
            g_ws4[i] = v;
        }
    }
}

// ---------------- exclusive scan (single launch, publish/poll) ----------------
// 98 blocks of 1024 threads: trivially co-resident on the SM pool, so the
// predecessor poll cannot deadlock. Block totals < 2^31; bit31 is the flag.

__global__ void __launch_bounds__(SCAN_BLOCK)
k_scan(int n) {
    __shared__ int warp_sums[32];
    __shared__ int s_prefix;
    int tid  = threadIdx.x;
    int i    = blockIdx.x * SCAN_BLOCK + tid;
    int lane = tid & 31, wid = tid >> 5;

    int v = (i < n) ? g_counts[i] : 0;

    int x = v;  // inclusive warp scan
    #pragma unroll
    for (int o = 1; o < 32; o <<= 1) {
        int y = __shfl_up_sync(0xFFFFFFFFu, x, o);
        if (lane >= o) x += y;
    }
    if (lane == 31) warp_sums[wid] = x;
    __syncthreads();

    if (wid == 0) {
        int w = warp_sums[lane];
        #pragma unroll
        for (int o = 1; o < 32; o <<= 1) {
            int y = __shfl_up_sync(0xFFFFFFFFu, w, o);
            if (lane >= o) w += y;
        }
        warp_sums[lane] = w;
        if (lane == 31)
            atomicExch(&g_pub[blockIdx.x], 0x80000000u | (unsigned)w);
    }
    __syncthreads();

    if (wid == 0) {
        int acc = 0;
        for (int b = lane; b < (int)blockIdx.x; b += 32) {
            unsigned int p;
            do { p = *(volatile unsigned int*)&g_pub[b]; }
            while (!(p & 0x80000000u));
            acc += (int)(p & 0x7FFFFFFFu);
        }
        #pragma unroll
        for (int o = 16; o > 0; o >>= 1)
            acc += __shfl_down_sync(0xFFFFFFFFu, acc, o);
        if (lane == 0) s_prefix = acc;
    }
    __syncthreads();

    int warp_off = (wid > 0) ? warp_sums[wid - 1] : 0;
    if (i < n) {
        int excl = s_prefix + warp_off + x - v;
        g_offsets[i] = excl;        // segment start
        g_cursor[i]  = excl + v;    // segment end
    }
}

// ---------------- scatter (atomic-free) ----------------

__global__ void __launch_bounds__(256)
k_scatter(const int4* __restrict__ src4,
          const int4* __restrict__ dst4, int n_quads,
          const int* __restrict__ src,
          const int* __restrict__ dst, int n_edges)
{
    int q = blockIdx.x * 256 + threadIdx.x;
    if (q < n_quads) {
        int4 s = __ldg(src4 + q);
        int4 d = __ldg(dst4 + q);
        int4 r = ((const int4*)g_rank)[q];
        g_edge_src[g_offsets[d.x] + r.x] = s.x;
        g_edge_src[g_offsets[d.y] + r.y] = s.y;
        g_edge_src[g_offsets[d.z] + r.z] = s.z;
        g_edge_src[g_offsets[d.w] + r.w] = s.w;
    }
    int t = n_quads * 4 + q;
    if (q < (n_edges - n_quads * 4))
        g_edge_src[g_offsets[dst[t]] + g_rank[t]] = src[t];

    // reset scan publish flags for the next graph replay
    if (blockIdx.x == 0 && threadIdx.x < MAX_SCAN_BLOCKS)
        g_pub[threadIdx.x] = 0u;
}

// ---------------- main gather-accumulate ----------------
// One warp per destination node; lane c owns float4 chunk c of the row.
// Edge ids are loaded coalesced (lane j -> edge base+j) and shfl-broadcast.

__global__ void __launch_bounds__(256)
k_gather(const float* __restrict__ ci,
         float4*      __restrict__ out4,
         int n_nodes)
{
    int gid  = blockIdx.x * blockDim.x + threadIdx.x;
    int node = gid >> 5;
    int c    = gid & 31;
    if (node >= n_nodes) return;           // warp-uniform (32 lanes per node)

    int base = g_offsets[node];
    int end  = g_cursor[node];

    float4 acc = make_float4(0.f, 0.f, 0.f, 0.f);

    for (int b = base; b < end; b += 32) {
        int m = end - b;
        if (m > 32) m = 32;
        int sl = (c < m) ? g_edge_src[b + c] : 0;   // coalesced chunk of ids

        int j = 0;
        for (; j + 3 < m; j += 4) {
            int s0 = __shfl_sync(0xFFFFFFFFu, sl, j);
            int s1 = __shfl_sync(0xFFFFFFFFu, sl, j + 1);
            int s2 = __shfl_sync(0xFFFFFFFFu, sl, j + 2);
            int s3 = __shfl_sync(0xFFFFFFFFu, sl, j + 3);
            float4 v0 = __ldg(&g_ws4[(int64_t)s0 * FEAT4 + c]);
            float4 v1 = __ldg(&g_ws4[(int64_t)s1 * FEAT4 + c]);
            float4 v2 = __ldg(&g_ws4[(int64_t)s2 * FEAT4 + c]);
            float4 v3 = __ldg(&g_ws4[(int64_t)s3 * FEAT4 + c]);
            acc.x += v0.x; acc.y += v0.y; acc.z += v0.z; acc.w += v0.w;
            acc.x += v1.x; acc.y += v1.y; acc.z += v1.z; acc.w += v1.w;
            acc.x += v2.x; acc.y += v2.y; acc.z += v2.z; acc.w += v2.w;
            acc.x += v3.x; acc.y += v3.y; acc.z += v3.z; acc.w += v3.w;
        }
        for (; j < m; j++) {
            int s0 = __shfl_sync(0xFFFFFFFFu, sl, j);
            float4 v0 = __ldg(&g_ws4[(int64_t)s0 * FEAT4 + c]);
            acc.x += v0.x; acc.y += v0.y; acc.z += v0.z; acc.w += v0.w;
        }
    }

    float mlt = __ldg(ci + node);
    acc.x *= mlt; acc.y *= mlt; acc.z *= mlt; acc.w *= mlt;
    out4[(int64_t)node * FEAT4 + c] = acc;

    // restore zero-counts invariant for the next graph replay
    if (c == 0) g_counts[node] = 0;
}

// ---------------- launch ----------------

extern "C" void kernel_launch(void* const* d_in, const int* in_sizes, int n_in,
                              void* d_out, int out_size)
{
    const float4* weight4 = (const float4*)d_in[0];
    const float*  cj      = (const float*)d_in[1];
    const float*  ci      = (const float*)d_in[2];
    const int*    src     = (const int*)d_in[3];
    const int*    dst     = (const int*)d_in[4];
    float4*       out4    = (float4*)d_out;

    int n_nodes = in_sizes[1];   // cj is [N,1]
    int n_edges = in_sizes[3];
    int n_quads = n_edges / 4;

    const int B = 256;
    int hist_blocks = (n_quads + B - 1) / B;
    int pre_blocks  = (n_nodes * FEAT4 + B - 1) / B;
    int quad_blocks = hist_blocks;
    int scan_blocks = (n_nodes + SCAN_BLOCK - 1) / SCAN_BLOCK;

    k_pre<<<hist_blocks + pre_blocks, B>>>(weight4, cj, (const int4*)dst, dst,
                                           n_quads, n_edges, n_nodes, hist_blocks);
    k_scan<<<scan_blocks, SCAN_BLOCK>>>(n_nodes);
    k_scatter<<<quad_blocks, B>>>((const int4*)src, (const int4*)dst, n_quads,
                                  src, dst, n_edges);

    int64_t total_threads = (int64_t)n_nodes * 32;
    int gather_blocks = (int)((total_threads + B - 1) / B);
    k_gather<<<gather_blocks, B>>>(ci, out4, n_nodes);
}